// round 4
// baseline (speedup 1.0000x reference)
#include <cuda_runtime.h>
#include <math.h>
#include <stdint.h>

#define BB 8
#define NN 2048
#define MM 2048
#define STRIDE 512            /* max sparse entries per row/col */
#define PAIRS (STRIDE / 2)
#define NITER 100

#define KFLOOR 1.9287498479639178e-22f   /* fp32(exp(-50)) */
#define MUV    4.8828125e-4f             /* 1/2048 */
#define EPSDIV 1e-8f

static __device__ __forceinline__ float uaf(unsigned x) { return __uint_as_float(x); }

// ---- static device scratch (no runtime allocations allowed) ----
__device__ uint4 g_rell4[(size_t)BB * PAIRS * NN];   // (j, Ktilde)     row-major (Kv phase)
__device__ uint4 g_cell4[(size_t)BB * PAIRS * MM];   // (i, Ktilde)     col-major (K^T u phase)
__device__ uint4 g_eell4[(size_t)BB * PAIRS * NN];   // (j, Ktilde*d)   row-major (emd epilogue)
__device__ int   g_ccnt[BB * MM];
__device__ float g_part[BB * 16];

// ---- dynamic SMEM layout (~47.3 KB, fits under the 48 KB default) ----
struct SK {
    float u[NN];
    float v[MM];
    float tx[MM], ty[MM], tz[MM];
    float part[1024];
    float slotsU[16], slotsV[16];
    float wred[32];
    float fscale[2];           // [0] = KFLOOR*S_v, [1] = KFLOOR*S_u
    int   rc[256], cc[256];
    unsigned long long mbu, mbv;
};

// ---- cluster / DSMEM / mbarrier helpers ----
static __device__ __forceinline__ uint32_t smem_u32(const void* p) {
    return (uint32_t)__cvta_generic_to_shared(p);
}
static __device__ __forceinline__ uint32_t mapa_sh(uint32_t addr, uint32_t rank) {
    uint32_t o;
    asm("mapa.shared::cluster.u32 %0, %1, %2;" : "=r"(o) : "r"(addr), "r"(rank));
    return o;
}
static __device__ __forceinline__ void st_async32(uint32_t daddr, unsigned v, uint32_t dmbar) {
    asm volatile("st.async.shared::cluster.mbarrier::complete_tx::bytes.u32 [%0], %1, [%2];"
                 :: "r"(daddr), "r"(v), "r"(dmbar) : "memory");
}
static __device__ __forceinline__ void bulk_s2s(uint32_t dst_cluster, uint32_t src_cta,
                                                uint32_t bytes, uint32_t dmbar_cluster) {
    asm volatile("cp.async.bulk.shared::cluster.shared::cta.mbarrier::complete_tx::bytes "
                 "[%0], [%1], %2, [%3];"
                 :: "r"(dst_cluster), "r"(src_cta), "r"(bytes), "r"(dmbar_cluster) : "memory");
}
static __device__ __forceinline__ void fence_proxy_async_cta() {
    asm volatile("fence.proxy.async.shared::cta;" ::: "memory");
}
static __device__ __forceinline__ void mb_init(uint32_t mb, uint32_t cnt) {
    asm volatile("mbarrier.init.shared.b64 [%0], %1;" :: "r"(mb), "r"(cnt) : "memory");
}
static __device__ __forceinline__ void mb_expect(uint32_t mb, uint32_t tx) {
    asm volatile("mbarrier.arrive.expect_tx.shared.b64 _, [%0], %1;" :: "r"(mb), "r"(tx) : "memory");
}
static __device__ __forceinline__ void mb_wait(uint32_t mb, uint32_t parity) {
    uint32_t done;
    asm volatile("{\n\t.reg .pred p;\n\t"
                 "mbarrier.try_wait.parity.acquire.cluster.shared::cta.b64 p, [%1], %2;\n\t"
                 "selp.b32 %0, 1, 0, p;\n\t}"
                 : "=r"(done) : "r"(mb), "r"(parity) : "memory");
    while (!done) {
        asm volatile("{\n\t.reg .pred p;\n\t"
                     "mbarrier.try_wait.parity.acquire.cluster.shared::cta.b64 p, [%1], %2, 0x989680;\n\t"
                     "selp.b32 %0, 1, 0, p;\n\t}"
                     : "=r"(done) : "r"(mb), "r"(parity) : "memory");
    }
}
#define CLUSTER_SYNC() do {                                                 \
    asm volatile("barrier.cluster.arrive.aligned;" ::: "memory");           \
    asm volatile("barrier.cluster.wait.aligned;"   ::: "memory");           \
} while (0)

// ---------------------------------------------------------------------------
// Fused: build sparse lists (cluster-local) -> 100 Sinkhorn iterations with
// bulk DSMEM broadcast -> EMD reduction. One cluster per batch (ncl = 8 or 16).
__global__ void __launch_bounds__(1024, 1)
sinkhorn_fused(const float* __restrict__ src, const float* __restrict__ tgt, int ncl) {
    extern __shared__ char raw[];
    SK* S = (SK*)raw;
    uint32_t crank;
    asm("mov.u32 %0, %%cluster_ctarank;" : "=r"(crank));
    const int tid   = threadIdx.x;
    const int lsh   = (ncl == 16) ? 7 : 8;       // log2(SLICE)
    const int SLICE = 1 << lsh;
    const int b     = blockIdx.x >> ((ncl == 16) ? 4 : 3);
    const int row0  = (int)crank * SLICE;
    const int warp  = tid >> 5, lane = tid & 31;

    // ---------------- stage 0: targets to SMEM, zero own ccnt slice ----------
    const float* T = tgt + (size_t)b * MM * 3;
    for (int j = tid; j < MM; j += 1024) {
        S->tx[j] = T[3 * j + 0];
        S->ty[j] = T[3 * j + 1];
        S->tz[j] = T[3 * j + 2];
    }
    if (tid < SLICE) g_ccnt[b * MM + row0 + tid] = 0;
    CLUSTER_SYNC();

    // ---------------- stage 1: build (this CTA's SLICE rows x all cols) -----
    const float* Sp = src + (size_t)b * NN * 3;
    uint2* rell2 = (uint2*)(g_rell4 + (size_t)b * PAIRS * NN);
    uint2* eell2 = (uint2*)(g_eell4 + (size_t)b * PAIRS * NN);
    uint2* cell2 = (uint2*)(g_cell4 + (size_t)b * PAIRS * MM);

    for (int ir = warp; ir < SLICE; ir += 32) {
        const int i = row0 + ir;
        const float sx = Sp[3 * i + 0], sy = Sp[3 * i + 1], sz = Sp[3 * i + 2];
        int rbase = 0;
        for (int j0 = 0; j0 < MM; j0 += 32) {
            const int j = j0 + lane;
            float dx = sx - S->tx[j];
            float dy = sy - S->ty[j];
            float dz = sz - S->tz[j];
            float s = fmaf(dx, dx, fmaf(dy, dy, dz * dz));
            bool pred = (s < 0.25f);
            unsigned mask = __ballot_sync(0xffffffffu, pred);
            if (pred) {
                float d = sqrtf(s);
                float kt = expf(-100.0f * d) - KFLOOR;
                int k = rbase + __popc(mask & ((1u << lane) - 1u));
                if (k < STRIDE) {
                    size_t i2 = ((size_t)(k >> 1) * NN + i) * 2 + (k & 1);
                    rell2[i2] = make_uint2((unsigned)j, __float_as_uint(kt));
                    eell2[i2] = make_uint2((unsigned)j, __float_as_uint(kt * d));
                }
                int kc = atomicAdd(&g_ccnt[b * MM + j], 1);
                if (kc < STRIDE)
                    cell2[((size_t)(kc >> 1) * MM + j) * 2 + (kc & 1)] =
                        make_uint2((unsigned)i, __float_as_uint(kt));
            }
            rbase += __popc(mask);
        }
        int cap = (rbase < STRIDE) ? rbase : STRIDE;
        if (lane == 0) {
            S->rc[ir] = cap;
            if (cap & 1) {   // cap==STRIDE is even, so this implies cap<STRIDE
                size_t i2 = ((size_t)(cap >> 1) * NN + i) * 2 + 1;
                rell2[i2] = make_uint2(0u, 0u);
                eell2[i2] = make_uint2(0u, 0u);
            }
        }
    }

    const uint32_t mbu = smem_u32(&S->mbu), mbv = smem_u32(&S->mbv);
    if (tid == 0) {
        mb_init(mbu, 1);
        mb_init(mbv, 1);
        S->fscale[0] = KFLOOR * (float)MM;   // S_v = 2048 at iter 0 (v = 1)
    }
    for (int j = tid; j < MM; j += 1024) S->v[j] = 1.0f;
    CLUSTER_SYNC();   // col atomics done cluster-wide; peers' mbarriers live

    // column counts for own col slice + odd-tail pad (only this CTA reads them)
    if (tid < SLICE) {
        int c = g_ccnt[b * MM + row0 + tid];
        if (c > STRIDE) c = STRIDE;
        S->cc[tid] = c;
        if (c & 1)
            cell2[((size_t)(c >> 1) * MM + (row0 + tid)) * 2 + 1] = make_uint2(0u, 0u);
    }
    __syncthreads();

    // ---------------- stage 2: 100 Sinkhorn iterations -----------------------
    const uint4* rell = g_rell4 + (size_t)b * PAIRS * NN;
    const uint4* cell = g_cell4 + (size_t)b * PAIRS * MM;
    const int lrow = tid & (SLICE - 1);
    const int sub  = tid >> lsh;
    const int nsub = 1024 >> lsh;
    const uint4* prow = rell + (row0 + lrow);
    const uint4* pcol = cell + (row0 + lrow);
    const int rnp = (S->rc[lrow] + 1) >> 1;
    const int cnp = (S->cc[lrow] + 1) >> 1;
    const uint32_t TXB = (uint32_t)(ncl - 1) * (uint32_t)SLICE * 4u + (uint32_t)ncl * 4u;
    const uint32_t ubase = smem_u32(S->u), vbase = smem_u32(S->v);
    const uint32_t sU = smem_u32(S->slotsU), sV = smem_u32(S->slotsV);
    const uint32_t uoff = ubase + (uint32_t)row0 * 4u;
    const uint32_t voff = vbase + (uint32_t)row0 * 4u;
    const int nw = SLICE >> 5;   // warps holding owner rows

    for (int iter = 0; iter < NITER; iter++) {
        const uint32_t par = (uint32_t)(iter & 1);

        // ---- phase A: u from v ----
        if (tid == 0) mb_expect(mbu, TXB);
        {
            float acc = 0.0f;
            for (int pp = sub; pp < rnp; pp += nsub) {
                uint4 e = prow[(size_t)pp * NN];
                acc = fmaf(uaf(e.y), S->v[e.x], acc);
                acc = fmaf(uaf(e.w), S->v[e.z], acc);
            }
            S->part[tid] = acc;
        }
        __syncthreads();
        if (tid < SLICE) {
            float tot = S->part[tid];
            for (int s2 = 1; s2 < nsub; s2++) tot += S->part[tid + (s2 << lsh)];
            float u = MUV / fmaxf(S->fscale[0] + tot, EPSDIV);
            S->u[row0 + tid] = u;
            float ws = u;
#pragma unroll
            for (int o = 16; o > 0; o >>= 1) ws += __shfl_xor_sync(0xffffffffu, ws, o);
            if (lane == 0) S->wred[warp] = ws;
        }
        __syncthreads();   // publishes local u slice + wred
        if (tid < 32) {
            float cs = (tid < nw) ? S->wred[tid] : 0.0f;
#pragma unroll
            for (int o = 16; o > 0; o >>= 1) cs += __shfl_xor_sync(0xffffffffu, cs, o);
            if (tid < ncl) {
                uint32_t rmb = mapa_sh(mbu, (uint32_t)tid);
                st_async32(mapa_sh(sU + crank * 4u, (uint32_t)tid), __float_as_uint(cs), rmb);
                if ((uint32_t)tid != crank) {
                    fence_proxy_async_cta();
                    bulk_s2s(mapa_sh(uoff, (uint32_t)tid), uoff, (uint32_t)SLICE * 4u, rmb);
                }
            }
        }
        mb_wait(mbu, par);
        if (tid < 32) {   // S_u -> fscale[1]; published by phase B's __syncthreads
            float s2 = (tid < ncl) ? S->slotsU[tid] : 0.0f;
#pragma unroll
            for (int o = 16; o > 0; o >>= 1) s2 += __shfl_xor_sync(0xffffffffu, s2, o);
            if (tid == 0) S->fscale[1] = KFLOOR * s2;
        }

        // ---- phase B: v from u ----
        if (tid == 0) mb_expect(mbv, TXB);
        {
            float acc = 0.0f;
            for (int pp = sub; pp < cnp; pp += nsub) {
                uint4 e = pcol[(size_t)pp * MM];
                acc = fmaf(uaf(e.y), S->u[e.x], acc);
                acc = fmaf(uaf(e.w), S->u[e.z], acc);
            }
            S->part[tid] = acc;
        }
        __syncthreads();
        if (tid < SLICE) {
            float tot = S->part[tid];
            for (int s2 = 1; s2 < nsub; s2++) tot += S->part[tid + (s2 << lsh)];
            float v = MUV / fmaxf(S->fscale[1] + tot, EPSDIV);
            S->v[row0 + tid] = v;
            float ws = v;
#pragma unroll
            for (int o = 16; o > 0; o >>= 1) ws += __shfl_xor_sync(0xffffffffu, ws, o);
            if (lane == 0) S->wred[warp] = ws;
        }
        __syncthreads();
        if (tid < 32) {
            float cs = (tid < nw) ? S->wred[tid] : 0.0f;
#pragma unroll
            for (int o = 16; o > 0; o >>= 1) cs += __shfl_xor_sync(0xffffffffu, cs, o);
            if (tid < ncl) {
                uint32_t rmb = mapa_sh(mbv, (uint32_t)tid);
                st_async32(mapa_sh(sV + crank * 4u, (uint32_t)tid), __float_as_uint(cs), rmb);
                if ((uint32_t)tid != crank) {
                    fence_proxy_async_cta();
                    bulk_s2s(mapa_sh(voff, (uint32_t)tid), voff, (uint32_t)SLICE * 4u, rmb);
                }
            }
        }
        mb_wait(mbv, par);
        if (tid < 32) {   // S_v -> fscale[0]; published by next phase A's __syncthreads
            float s2 = (tid < ncl) ? S->slotsV[tid] : 0.0f;
#pragma unroll
            for (int o = 16; o > 0; o >>= 1) s2 += __shfl_xor_sync(0xffffffffu, s2, o);
            if (tid == 0) S->fscale[0] = KFLOOR * s2;
        }
    }

    CLUSTER_SYNC();   // no CTA proceeds/exits with peer bulk traffic in flight

    // ---------------- stage 3: EMD epilogue (u, v, targets all in SMEM) ------
    // emd_b = sum_i u_i * ( KFLOOR * sum_j d_ij v_j + sum_sparse (K~ d)_ij v_j )
    const uint4* eell = g_eell4 + (size_t)b * PAIRS * NN;
    float wacc = 0.0f;
    for (int ir = warp; ir < SLICE; ir += 32) {
        const int i = row0 + ir;
        const float sx = Sp[3 * i + 0], sy = Sp[3 * i + 1], sz = Sp[3 * i + 2];
        const float ui = S->u[i];
        float dacc = 0.0f;
        for (int j0 = 0; j0 < MM; j0 += 32) {
            const int j = j0 + lane;
            float dx = sx - S->tx[j];
            float dy = sy - S->ty[j];
            float dz = sz - S->tz[j];
            float s = fmaf(dx, dx, fmaf(dy, dy, dz * dz));
            dacc = fmaf(sqrtf(s), S->v[j], dacc);
        }
        float sacc = 0.0f;
        const int np = (S->rc[ir] + 1) >> 1;
        const uint4* p = eell + i;
        for (int pp = lane; pp < np; pp += 32) {
            uint4 e = p[(size_t)pp * NN];
            sacc = fmaf(uaf(e.y), S->v[e.x], sacc);
            sacc = fmaf(uaf(e.w), S->v[e.z], sacc);
        }
        float tot = fmaf(KFLOOR, dacc, sacc);
#pragma unroll
        for (int o = 16; o > 0; o >>= 1) tot += __shfl_xor_sync(0xffffffffu, tot, o);
        if (lane == 0) wacc = fmaf(ui, tot, wacc);
    }
    if (lane == 0) S->wred[warp] = wacc;
    __syncthreads();
    if (tid == 0) {
        float s = 0.0f;
        for (int w = 0; w < 32; w++) s += S->wred[w];
        g_part[blockIdx.x] = s;
    }
}

// ---------------------------------------------------------------------------
__global__ void finalize_kernel(float* out, int n) {
    __shared__ float r[4];
    float s = 0.0f;
    for (int i = threadIdx.x; i < n; i += 128) s += g_part[i];
#pragma unroll
    for (int o = 16; o > 0; o >>= 1) s += __shfl_xor_sync(0xffffffffu, s, o);
    if ((threadIdx.x & 31) == 0) r[threadIdx.x >> 5] = s;
    __syncthreads();
    if (threadIdx.x == 0) out[0] = (r[0] + r[1] + r[2] + r[3]) * (1.0f / BB);
}

// ---------------------------------------------------------------------------
extern "C" void kernel_launch(void* const* d_in, const int* in_sizes, int n_in,
                              void* d_out, int out_size) {
    (void)in_sizes; (void)n_in; (void)out_size;
    const float* src = (const float*)d_in[0];
    const float* tgt = (const float*)d_in[1];
    float* out = (float*)d_out;

    cudaLaunchConfig_t cfg = {};
    cfg.blockDim = dim3(1024, 1, 1);
    cfg.dynamicSmemBytes = (unsigned)sizeof(SK);
    cfg.stream = 0;
    cfg.numAttrs = 0;

    int cl = 8;
    if (cudaFuncSetAttribute((const void*)sinkhorn_fused,
                             cudaFuncAttributeNonPortableClusterSizeAllowed, 1) == cudaSuccess) {
        int maxc = 0;
        cfg.gridDim = dim3(BB * 16, 1, 1);
        if (cudaOccupancyMaxPotentialClusterSize(&maxc, (const void*)sinkhorn_fused, &cfg)
                == cudaSuccess && maxc >= 16)
            cl = 16;
    }

    cudaLaunchAttribute at;
    at.id = cudaLaunchAttributeClusterDimension;
    at.val.clusterDim.x = (unsigned)cl;
    at.val.clusterDim.y = 1;
    at.val.clusterDim.z = 1;
    cfg.gridDim = dim3(BB * cl, 1, 1);
    cfg.attrs = &at;
    cfg.numAttrs = 1;
    cudaLaunchKernelEx(&cfg, sinkhorn_fused, src, tgt, cl);

    finalize_kernel<<<1, 128>>>(out, BB * cl);
}

// round 5
// speedup vs baseline: 1.6062x; 1.6062x over previous
#include <cuda_runtime.h>
#include <math.h>
#include <stdint.h>

#define BB 8
#define NN 2048
#define MM 2048
#define STRIDE 512            /* max sparse entries per row/col in gmem ELL */
#define PAIRS (STRIDE / 2)
#define NITER 100
#define CL 8                  /* CTAs per cluster (= per batch) */
#define SLICE 256             /* rows/cols owned per CTA        */
#define CAP 7680              /* smem CSR entry capacity per list (mean ~5900, +23 sigma) */
#define TXB 8448u             /* per-phase incoming bytes: 2048*4 + 64*4 */

#define KFLOOR 1.9287498479639178e-22f   /* fp32(exp(-50)) */
#define MUV    4.8828125e-4f             /* 1/2048 */
#define EPSDIV 1e-8f

static __device__ __forceinline__ float uaf(unsigned x) { return __uint_as_float(x); }

// ---- static device scratch (no runtime allocations allowed) ----
__device__ uint4 g_rell4[(size_t)BB * PAIRS * NN];   // (j, Ktilde)    row-major ELL
__device__ uint4 g_cell4[(size_t)BB * PAIRS * MM];   // (i, Ktilde)    col-major ELL
__device__ uint4 g_eell4[(size_t)BB * PAIRS * NN];   // (j, Ktilde*d)  row-major ELL (emd)
__device__ int   g_ccnt[BB * MM];
__device__ float g_part[BB * CL];

// ---- dynamic SMEM layout (~147.6 KB) ----
struct SK {
    float u[NN];               // full u, replicated per CTA
    float v[MM];               // full v, replicated per CTA
    float part[1024];
    float slotsU[64], slotsV[64];   // 8 ranks x 8 owner warps
    float wred[32];
    float fscale[2];           // [0]=KFLOOR*S_v  [1]=KFLOOR*S_u
    int   rowOff[SLICE + 1], colOff[SLICE + 1];
    int   cntR[SLICE], cntC[SLICE];
    unsigned long long mbu, mbv;
    unsigned long long _pad;   // keep uint4 arrays 16B-aligned
    uint4 rcsr4[CAP / 2];      // row CSR (pairs of uint2 entries); aliased as txyz in build/epilogue
    uint4 ccsr4[CAP / 2];      // col CSR
};

// ---- cluster / DSMEM / mbarrier helpers ----
static __device__ __forceinline__ uint32_t smem_u32(const void* p) {
    return (uint32_t)__cvta_generic_to_shared(p);
}
static __device__ __forceinline__ uint32_t mapa_sh(uint32_t addr, uint32_t rank) {
    uint32_t o;
    asm("mapa.shared::cluster.u32 %0, %1, %2;" : "=r"(o) : "r"(addr), "r"(rank));
    return o;
}
static __device__ __forceinline__ void st_async32(uint32_t daddr, unsigned v, uint32_t dmbar) {
    asm volatile("st.async.shared::cluster.mbarrier::complete_tx::bytes.u32 [%0], %1, [%2];"
                 :: "r"(daddr), "r"(v), "r"(dmbar) : "memory");
}
static __device__ __forceinline__ void st_async64(uint32_t daddr, unsigned long long v, uint32_t dmbar) {
    asm volatile("st.async.shared::cluster.mbarrier::complete_tx::bytes.u64 [%0], %1, [%2];"
                 :: "r"(daddr), "l"(v), "r"(dmbar) : "memory");
}
static __device__ __forceinline__ void mb_init(uint32_t mb, uint32_t cnt) {
    asm volatile("mbarrier.init.shared.b64 [%0], %1;" :: "r"(mb), "r"(cnt) : "memory");
}
static __device__ __forceinline__ void mb_expect(uint32_t mb, uint32_t tx) {
    asm volatile("mbarrier.arrive.expect_tx.shared.b64 _, [%0], %1;" :: "r"(mb), "r"(tx) : "memory");
}
static __device__ __forceinline__ void mb_wait(uint32_t mb, uint32_t parity) {
    uint32_t done;
    asm volatile("{\n\t.reg .pred p;\n\t"
                 "mbarrier.try_wait.parity.acquire.cluster.shared::cta.b64 p, [%1], %2;\n\t"
                 "selp.b32 %0, 1, 0, p;\n\t}"
                 : "=r"(done) : "r"(mb), "r"(parity) : "memory");
    while (!done) {
        asm volatile("{\n\t.reg .pred p;\n\t"
                     "mbarrier.try_wait.parity.acquire.cluster.shared::cta.b64 p, [%1], %2, 0x989680;\n\t"
                     "selp.b32 %0, 1, 0, p;\n\t}"
                     : "=r"(done) : "r"(mb), "r"(parity) : "memory");
    }
}
#define CLUSTER_SYNC() do {                                                 \
    asm volatile("barrier.cluster.arrive.aligned;" ::: "memory");           \
    asm volatile("barrier.cluster.wait.aligned;"   ::: "memory");           \
} while (0)

// ---------------------------------------------------------------------------
// Fused: build sparse lists -> smem CSR -> 100 Sinkhorn iterations (all-SMEM
// gather + st.async broadcast) -> EMD reduction. One 8-CTA cluster per batch.
__global__ void __launch_bounds__(1024, 1) __cluster_dims__(CL, 1, 1)
sinkhorn_fused(const float* __restrict__ src, const float* __restrict__ tgt) {
    extern __shared__ char raw[];
    SK* S = (SK*)raw;
    uint32_t crank;
    asm("mov.u32 %0, %%cluster_ctarank;" : "=r"(crank));
    const int tid  = threadIdx.x;
    const int b    = blockIdx.x >> 3;
    const int row0 = (int)crank * SLICE;
    const int warp = tid >> 5, lane = tid & 31;

    // txyz aliases the row-CSR region during build and epilogue
    float* tx = (float*)S->rcsr4;
    float* ty = tx + MM;
    float* tz = tx + 2 * MM;

    // ---------------- stage 0: targets -> smem; zero own ccnt slice ----------
    const float* T = tgt + (size_t)b * MM * 3;
    for (int j = tid; j < MM; j += 1024) {
        tx[j] = T[3 * j + 0];
        ty[j] = T[3 * j + 1];
        tz[j] = T[3 * j + 2];
        S->v[j] = 1.0f;
    }
    if (tid < SLICE) g_ccnt[b * MM + row0 + tid] = 0;
    if (tid == 0) {
        mb_init(smem_u32(&S->mbu), 1);
        mb_init(smem_u32(&S->mbv), 1);
        S->fscale[0] = KFLOOR * (float)MM;   // S_v = 2048 at iter 0
    }
    CLUSTER_SYNC();

    // ---------------- stage 1: build (own SLICE rows x all cols) -------------
    const float* Sp = src + (size_t)b * NN * 3;
    uint2* rell2 = (uint2*)(g_rell4 + (size_t)b * PAIRS * NN);
    uint2* eell2 = (uint2*)(g_eell4 + (size_t)b * PAIRS * NN);
    uint2* cell2 = (uint2*)(g_cell4 + (size_t)b * PAIRS * MM);

    for (int ir = warp; ir < SLICE; ir += 32) {
        const int i = row0 + ir;
        const float sx = Sp[3 * i + 0], sy = Sp[3 * i + 1], sz = Sp[3 * i + 2];
        int rbase = 0;
        for (int j0 = 0; j0 < MM; j0 += 32) {
            const int j = j0 + lane;
            float dx = sx - tx[j];
            float dy = sy - ty[j];
            float dz = sz - tz[j];
            float s = fmaf(dx, dx, fmaf(dy, dy, dz * dz));
            bool pred = (s < 0.25f);
            unsigned mask = __ballot_sync(0xffffffffu, pred);
            if (pred) {
                float d = sqrtf(s);
                float kt = expf(-100.0f * d) - KFLOOR;
                int k = rbase + __popc(mask & ((1u << lane) - 1u));
                if (k < STRIDE) {
                    size_t i2 = ((size_t)(k >> 1) * NN + i) * 2 + (k & 1);
                    rell2[i2] = make_uint2((unsigned)j, __float_as_uint(kt));
                    eell2[i2] = make_uint2((unsigned)j, __float_as_uint(kt * d));
                }
                int kc = atomicAdd(&g_ccnt[b * MM + j], 1);
                if (kc < STRIDE)
                    cell2[((size_t)(kc >> 1) * MM + j) * 2 + (kc & 1)] =
                        make_uint2((unsigned)i, __float_as_uint(kt));
            }
            rbase += __popc(mask);
        }
        int cap = (rbase < STRIDE) ? rbase : STRIDE;
        if (lane == 0) {
            S->cntR[ir] = cap;
            if (cap & 1) {   // zero-pad ELL odd tail (cap==STRIDE is even)
                size_t i2 = ((size_t)(cap >> 1) * NN + i) * 2 + 1;
                rell2[i2] = make_uint2(0u, 0u);
                eell2[i2] = make_uint2(0u, 0u);
            }
        }
    }
    CLUSTER_SYNC();   // cluster-wide col atomics + gmem ELL writes complete

    // ---------------- stage 1.5: offsets + smem CSR fill ---------------------
    if (tid < SLICE) {
        int c = g_ccnt[b * MM + row0 + tid];
        S->cntC[tid] = (c < STRIDE) ? c : STRIDE;
    }
    __syncthreads();
    if (tid == 0) {
        int accR = 0, accC = 0;
        S->rowOff[0] = 0;
        S->colOff[0] = 0;
        for (int i = 0; i < SLICE; i++) {
            int cp = (S->cntR[i] + 1) & ~1;
            accR = min(accR + cp, CAP);
            S->rowOff[i + 1] = accR;
            cp = (S->cntC[i] + 1) & ~1;
            accC = min(accC + cp, CAP);
            S->colOff[i + 1] = accC;
        }
    }
    __syncthreads();
    {
        const int l = tid & (SLICE - 1);
        const int sb = tid >> 8;                 // 0..3
        uint2* rcsr = (uint2*)S->rcsr4;          // NOTE: overwrites tx/ty/tz
        uint2* ccsr = (uint2*)S->ccsr4;
        const uint4* rell = g_rell4 + (size_t)b * PAIRS * NN;
        const uint4* cell = g_cell4 + (size_t)b * PAIRS * MM;
        {
            int off = S->rowOff[l], np = S->rowOff[l + 1] - off;
            for (int pp = sb; pp < (np >> 1); pp += 4) {
                uint4 e = rell[(size_t)pp * NN + (row0 + l)];
                rcsr[off + 2 * pp]     = make_uint2(e.x, e.y);
                rcsr[off + 2 * pp + 1] = make_uint2(e.z, e.w);   // ELL zero-padded
            }
        }
        {
            int off = S->colOff[l], np = S->colOff[l + 1] - off;
            int c = S->cntC[l];
            for (int pp = sb; pp < (np >> 1); pp += 4) {
                uint4 e = cell[(size_t)pp * MM + (row0 + l)];
                ccsr[off + 2 * pp] = make_uint2(e.x, e.y);
                ccsr[off + 2 * pp + 1] = (2 * pp + 1 < c) ? make_uint2(e.z, e.w)
                                                          : make_uint2(0u, 0u);
            }
        }
    }
    __syncthreads();

    // ---------------- stage 2: 100 Sinkhorn iterations (all-SMEM) ------------
    const int lrow = tid & (SLICE - 1);
    const int sub  = tid >> 8;               // 0..3
    const uint4* br = S->rcsr4 + (S->rowOff[lrow] >> 1);
    const uint4* bc = S->ccsr4 + (S->colOff[lrow] >> 1);
    const int rnp = (S->rowOff[lrow + 1] - S->rowOff[lrow]) >> 1;   // uint4 pair slots
    const int cnp = (S->colOff[lrow + 1] - S->colOff[lrow]) >> 1;
    const uint32_t mbu = smem_u32(&S->mbu), mbv = smem_u32(&S->mbv);
    const uint32_t ubase = smem_u32(S->u), vbase = smem_u32(S->v);
    const uint32_t sU = smem_u32(S->slotsU), sV = smem_u32(S->slotsV);
    const uint32_t uaddr = ubase + (uint32_t)(row0 + tid) * 4u;   // owner's dest offset
    const uint32_t vaddr = vbase + (uint32_t)(row0 + tid) * 4u;

    for (int iter = 0; iter < NITER; iter++) {
        const uint32_t par = (uint32_t)(iter & 1);

        // ---- phase A: u from v ----
        if (tid == 0) mb_expect(mbu, TXB);
        {
            float acc = 0.0f;
            for (int pk = sub; pk < rnp; pk += 4) {
                uint4 e = br[pk];
                acc = fmaf(uaf(e.y), S->v[e.x], acc);
                acc = fmaf(uaf(e.w), S->v[e.z], acc);
            }
            S->part[tid] = acc;
        }
        __syncthreads();   // publishes part[] (and fscale[0] from prev iter)
        if (tid < SLICE) {
            float tot = S->part[tid] + S->part[tid + 256] + S->part[tid + 512] + S->part[tid + 768];
            float u = MUV / fmaxf(S->fscale[0] + tot, EPSDIV);
            float ws = u;
#pragma unroll
            for (int o = 16; o > 0; o >>= 1) ws += __shfl_xor_sync(0xffffffffu, ws, o);
            float uhi = __shfl_down_sync(0xffffffffu, u, 1);
            if (!(tid & 1)) {
                unsigned long long pk =
                    ((unsigned long long)__float_as_uint(uhi) << 32) | __float_as_uint(u);
#pragma unroll
                for (uint32_t r = 0; r < CL; r++)
                    st_async64(mapa_sh(uaddr, r), pk, mapa_sh(mbu, r));
            }
            if (lane == 0) {
                uint32_t sa = sU + (crank * 8u + (uint32_t)warp) * 4u;
#pragma unroll
                for (uint32_t r = 0; r < CL; r++)
                    st_async32(mapa_sh(sa, r), __float_as_uint(ws), mapa_sh(mbu, r));
            }
        }
        mb_wait(mbu, par);
        if (tid < 32) {   // S_u -> fscale[1]; consumed after phase B's barrier
            float s2 = S->slotsU[tid] + S->slotsU[tid + 32];
#pragma unroll
            for (int o = 16; o > 0; o >>= 1) s2 += __shfl_xor_sync(0xffffffffu, s2, o);
            if (tid == 0) S->fscale[1] = KFLOOR * s2;
        }

        // ---- phase B: v from u ----
        if (tid == 0) mb_expect(mbv, TXB);
        {
            float acc = 0.0f;
            for (int pk = sub; pk < cnp; pk += 4) {
                uint4 e = bc[pk];
                acc = fmaf(uaf(e.y), S->u[e.x], acc);
                acc = fmaf(uaf(e.w), S->u[e.z], acc);
            }
            S->part[tid] = acc;
        }
        __syncthreads();   // publishes part[] and fscale[1]
        if (tid < SLICE) {
            float tot = S->part[tid] + S->part[tid + 256] + S->part[tid + 512] + S->part[tid + 768];
            float v = MUV / fmaxf(S->fscale[1] + tot, EPSDIV);
            float ws = v;
#pragma unroll
            for (int o = 16; o > 0; o >>= 1) ws += __shfl_xor_sync(0xffffffffu, ws, o);
            float vhi = __shfl_down_sync(0xffffffffu, v, 1);
            if (!(tid & 1)) {
                unsigned long long pk =
                    ((unsigned long long)__float_as_uint(vhi) << 32) | __float_as_uint(v);
#pragma unroll
                for (uint32_t r = 0; r < CL; r++)
                    st_async64(mapa_sh(vaddr, r), pk, mapa_sh(mbv, r));
            }
            if (lane == 0) {
                uint32_t sa = sV + (crank * 8u + (uint32_t)warp) * 4u;
#pragma unroll
                for (uint32_t r = 0; r < CL; r++)
                    st_async32(mapa_sh(sa, r), __float_as_uint(ws), mapa_sh(mbv, r));
            }
        }
        mb_wait(mbv, par);
        if (tid < 32) {   // S_v -> fscale[0]; consumed after next phase A barrier
            float s2 = S->slotsV[tid] + S->slotsV[tid + 32];
#pragma unroll
            for (int o = 16; o > 0; o >>= 1) s2 += __shfl_xor_sync(0xffffffffu, s2, o);
            if (tid == 0) S->fscale[0] = KFLOOR * s2;
        }
    }

    CLUSTER_SYNC();   // all peer traffic drained before teardown / CSR overwrite

    // ---------------- stage 3: EMD epilogue ----------------------------------
    // emd_b = sum_i u_i * ( KFLOOR * sum_j d_ij v_j + sum_sparse (K~ d)_ij v_j )
    for (int j = tid; j < MM; j += 1024) {   // reload targets over the CSR region
        tx[j] = T[3 * j + 0];
        ty[j] = T[3 * j + 1];
        tz[j] = T[3 * j + 2];
    }
    __syncthreads();

    const uint4* eell = g_eell4 + (size_t)b * PAIRS * NN;
    float wacc = 0.0f;
    for (int ir = warp; ir < SLICE; ir += 32) {
        const int i = row0 + ir;
        const float sx = Sp[3 * i + 0], sy = Sp[3 * i + 1], sz = Sp[3 * i + 2];
        const float ui = S->u[i];
        float dacc = 0.0f;
        for (int j0 = 0; j0 < MM; j0 += 32) {
            const int j = j0 + lane;
            float dx = sx - tx[j];
            float dy = sy - ty[j];
            float dz = sz - tz[j];
            float s = fmaf(dx, dx, fmaf(dy, dy, dz * dz));
            dacc = fmaf(sqrtf(s), S->v[j], dacc);
        }
        float sacc = 0.0f;
        const int np = (S->cntR[ir] + 1) >> 1;   // uint4 pair slots (zero-padded)
        const uint4* p = eell + i;
        for (int pp = lane; pp < np; pp += 32) {
            uint4 e = p[(size_t)pp * NN];
            sacc = fmaf(uaf(e.y), S->v[e.x], sacc);
            sacc = fmaf(uaf(e.w), S->v[e.z], sacc);
        }
        float tot = fmaf(KFLOOR, dacc, sacc);
#pragma unroll
        for (int o = 16; o > 0; o >>= 1) tot += __shfl_xor_sync(0xffffffffu, tot, o);
        if (lane == 0) wacc = fmaf(ui, tot, wacc);
    }
    if (lane == 0) S->wred[warp] = wacc;
    __syncthreads();
    if (tid == 0) {
        float s = 0.0f;
        for (int w = 0; w < 32; w++) s += S->wred[w];
        g_part[blockIdx.x] = s;
    }
}

// ---------------------------------------------------------------------------
__global__ void finalize_kernel(float* out) {
    __shared__ float r[2];
    float s = 0.0f;
    for (int i = threadIdx.x; i < BB * CL; i += 64) s += g_part[i];
#pragma unroll
    for (int o = 16; o > 0; o >>= 1) s += __shfl_xor_sync(0xffffffffu, s, o);
    if ((threadIdx.x & 31) == 0) r[threadIdx.x >> 5] = s;
    __syncthreads();
    if (threadIdx.x == 0) out[0] = (r[0] + r[1]) * (1.0f / BB);
}

// ---------------------------------------------------------------------------
extern "C" void kernel_launch(void* const* d_in, const int* in_sizes, int n_in,
                              void* d_out, int out_size) {
    (void)in_sizes; (void)n_in; (void)out_size;
    const float* src = (const float*)d_in[0];
    const float* tgt = (const float*)d_in[1];
    float* out = (float*)d_out;

    cudaFuncSetAttribute(sinkhorn_fused, cudaFuncAttributeMaxDynamicSharedMemorySize,
                         (int)sizeof(SK));
    sinkhorn_fused<<<BB * CL, 1024, sizeof(SK)>>>(src, tgt);
    finalize_kernel<<<1, 64>>>(out);
}